// round 3
// baseline (speedup 1.0000x reference)
#include <cuda_runtime.h>
#include <cuda_bf16.h>

#define NN 20000
#define NE 640000
#define F  128
#define UN 8                      // nodes per tile in MLP kernel (20000 % 8 == 0)
#define NGROUPS (NN / UN)         // 2500

// ---------------- scratch (device globals; no allocations allowed) ----------
__device__ __align__(16) float g_agg[NN * F];   // aggregated (mean) features
__device__ __align__(16) float g_h[NN * F];     // hidden features after relu
__device__ float g_inv[NN];       // 1 / max(indegree, 1)
__device__ int   g_cnt[NN];
__device__ int   g_off[NN + 1];   // CSR offsets by dst
__device__ int   g_cur[NN];       // fill cursors
__device__ int   g_esrc[NE];      // src ids grouped by dst
__device__ int   g_is64;          // 1 if edge_index is int64, 0 if int32

// ---------------- dtype detection -------------------------------------------
// int64 node ids < 2^31 have zero high words at odd int32 indices; int32 data
// has uniform node ids there (P[128 zeros] ~ 0).
__global__ void k_detect(const int* __restrict__ ei32) {
    int acc = 0;
#pragma unroll
    for (int i = 0; i < 128; ++i) acc |= ei32[2 * i + 1];
    g_is64 = (acc == 0) ? 1 : 0;
}

__device__ __forceinline__ int load_idx(const void* ei, int pos) {
    if (g_is64) return (int)((const long long*)ei)[pos];
    return ((const int*)ei)[pos];
}

// ---------------- CSR build -------------------------------------------------
__global__ void k_zero_cnt() {
    int i = blockIdx.x * blockDim.x + threadIdx.x;
    if (i < NN) g_cnt[i] = 0;
}

__global__ void k_count(const void* __restrict__ ei) {
    int e = blockIdx.x * blockDim.x + threadIdx.x;
    if (e < NE) {
        int dst = load_idx(ei, NE + e);
        if ((unsigned)dst < NN) atomicAdd(&g_cnt[dst], 1);
    }
}

// single-block shuffle-based scan of 20000 counts -> offsets, cursors, 1/deg
__global__ void k_scan() {
    __shared__ int wsum[32];
    __shared__ int carry;
    int tid = threadIdx.x, lane = tid & 31, wid = tid >> 5;
    if (tid == 0) { carry = 0; g_off[0] = 0; }
    __syncthreads();
    for (int base = 0; base < NN; base += 1024) {
        int i = base + tid;
        int v = (i < NN) ? g_cnt[i] : 0;
        int s = v;
#pragma unroll
        for (int d = 1; d < 32; d <<= 1) {
            int t = __shfl_up_sync(0xffffffffu, s, d);
            if (lane >= d) s += t;
        }
        if (lane == 31) wsum[wid] = s;
        __syncthreads();
        if (wid == 0) {
            int ws = wsum[lane];
#pragma unroll
            for (int d = 1; d < 32; d <<= 1) {
                int t = __shfl_up_sync(0xffffffffu, ws, d);
                if (lane >= d) ws += t;
            }
            wsum[lane] = ws;
        }
        __syncthreads();
        int inc = s + (wid ? wsum[wid - 1] : 0);   // inclusive scan within chunk
        int c = carry;
        if (i < NN) {
            g_off[i + 1] = c + inc;
            g_cur[i]     = c + inc - v;            // exclusive start
            g_inv[i]     = 1.0f / (float)(v > 0 ? v : 1);
        }
        __syncthreads();
        if (tid == 1023) carry = c + wsum[31];
        __syncthreads();
    }
}

__global__ void k_fill(const void* __restrict__ ei) {
    int e = blockIdx.x * blockDim.x + threadIdx.x;
    if (e < NE) {
        int dst = load_idx(ei, NE + e);
        int src = load_idx(ei, e);
        if ((unsigned)dst < NN && (unsigned)src < NN) {
            int p = atomicAdd(&g_cur[dst], 1);
            g_esrc[p] = src;
        }
    }
}

// ---------------- mean aggregation: one warp per dst node -------------------
// use_h: 0 -> gather from external x, 1 -> gather from g_h. Writes g_agg.
__global__ void k_agg(const float4* __restrict__ xext, int use_h) {
    int warp = (blockIdx.x * blockDim.x + threadIdx.x) >> 5;
    int lane = threadIdx.x & 31;
    if (warp >= NN) return;
    const float4* __restrict__ feat = use_h ? (const float4*)g_h : xext;
    int beg = g_off[warp], end = g_off[warp + 1];
    float4 acc = make_float4(0.f, 0.f, 0.f, 0.f);
    for (int e0 = beg; e0 < end; e0 += 32) {
        int n = min(32, end - e0);
        int myid = (lane < n) ? g_esrc[e0 + lane] : 0;
        for (int j = 0; j < n; ++j) {
            int s = __shfl_sync(0xffffffffu, myid, j);
            float4 v = feat[s * 32 + lane];
            acc.x += v.x; acc.y += v.y; acc.z += v.z; acc.w += v.w;
        }
    }
    float inv = g_inv[warp];
    acc.x *= inv; acc.y *= inv; acc.z *= inv; acc.w *= inv;
    ((float4*)g_agg)[warp * 32 + lane] = acc;
}

// ---------------- fused (g_agg @ W + b) -> relu -> g_h ----------------------
// gridDim.y = 2 column halves. Block: 128 threads. Thread owns output column
// col = (tid&63) + 64*half and 4 of the 8 tile nodes (sub = tid>>6).
// W half staged in smem [k][jj] (32 KB static), input tile 4 KB.
__global__ void __launch_bounds__(128) k_mlp(const float* __restrict__ W,
                                             const float* __restrict__ b) {
    __shared__ float  Ws[F * 64];       // [k][jj]
    __shared__ float4 Ins[UN * 32];     // [u][c]
    int tid  = threadIdx.x;
    int half = blockIdx.y;
    int jj   = tid & 63;
    int col  = jj + 64 * half;
    int u0   = (tid >> 6) * 4;

    for (int idx = tid; idx < F * 64; idx += 128) {
        int k = idx >> 6, j = idx & 63;
        Ws[idx] = W[k * F + j + 64 * half];
    }
    float bj = b[col];

    const float4* __restrict__ in4 = (const float4*)g_agg;
    for (int g = blockIdx.x; g < NGROUPS; g += gridDim.x) {
        int n0 = g * UN;
        __syncthreads();   // Ws ready (first iter) / Ins reuse (later iters)
        for (int i = tid; i < UN * 32; i += 128)
            Ins[i] = in4[(n0 + (i >> 5)) * 32 + (i & 31)];
        __syncthreads();

        float acc0 = 0.f, acc1 = 0.f, acc2 = 0.f, acc3 = 0.f;
#pragma unroll 8
        for (int k4 = 0; k4 < 32; ++k4) {
            float w0 = Ws[(4 * k4 + 0) * 64 + jj];
            float w1 = Ws[(4 * k4 + 1) * 64 + jj];
            float w2 = Ws[(4 * k4 + 2) * 64 + jj];
            float w3 = Ws[(4 * k4 + 3) * 64 + jj];
            float4 v0 = Ins[(u0 + 0) * 32 + k4];
            float4 v1 = Ins[(u0 + 1) * 32 + k4];
            float4 v2 = Ins[(u0 + 2) * 32 + k4];
            float4 v3 = Ins[(u0 + 3) * 32 + k4];
            acc0 += v0.x * w0 + v0.y * w1 + v0.z * w2 + v0.w * w3;
            acc1 += v1.x * w0 + v1.y * w1 + v1.z * w2 + v1.w * w3;
            acc2 += v2.x * w0 + v2.y * w1 + v2.z * w2 + v2.w * w3;
            acc3 += v3.x * w0 + v3.y * w1 + v3.z * w2 + v3.w * w3;
        }
        float r0 = acc0 + bj, r1 = acc1 + bj, r2 = acc2 + bj, r3 = acc3 + bj;
        g_h[(n0 + u0 + 0) * F + col] = r0 > 0.f ? r0 : 0.f;
        g_h[(n0 + u0 + 1) * F + col] = r1 > 0.f ? r1 : 0.f;
        g_h[(n0 + u0 + 2) * F + col] = r2 > 0.f ? r2 : 0.f;
        g_h[(n0 + u0 + 3) * F + col] = r3 > 0.f ? r3 : 0.f;
    }
}

// ---------------- final projection 128 -> 2 ---------------------------------
__global__ void k_final(const float* __restrict__ W3, const float* __restrict__ b3,
                        float* __restrict__ out) {
    int warp = (blockIdx.x * blockDim.x + threadIdx.x) >> 5;
    int lane = threadIdx.x & 31;
    if (warp >= NN) return;
    float4 v = ((const float4*)g_h)[warp * 32 + lane];
    // W3 row-major [128][2]; lane covers k = 4*lane .. 4*lane+3
    float4 wa = ((const float4*)W3)[lane * 2 + 0]; // k0:{o0,o1}, k1:{o0,o1}
    float4 wb = ((const float4*)W3)[lane * 2 + 1]; // k2:{o0,o1}, k3:{o0,o1}
    float p0 = v.x * wa.x + v.y * wa.z + v.z * wb.x + v.w * wb.z;
    float p1 = v.x * wa.y + v.y * wa.w + v.z * wb.y + v.w * wb.w;
#pragma unroll
    for (int d = 16; d; d >>= 1) {
        p0 += __shfl_down_sync(0xffffffffu, p0, d);
        p1 += __shfl_down_sync(0xffffffffu, p1, d);
    }
    if (lane == 0) {
        out[warp * 2 + 0] = p0 + b3[0];
        out[warp * 2 + 1] = p1 + b3[1];
    }
}

// ---------------- launch: kernel launches ONLY ------------------------------
extern "C" void kernel_launch(void* const* d_in, const int* in_sizes, int n_in,
                              void* d_out, int out_size) {
    const float* x  = (const float*)d_in[0];
    const void*  ei = d_in[1];
    const float* W1 = (const float*)d_in[2];
    const float* b1 = (const float*)d_in[3];
    const float* W2 = (const float*)d_in[4];
    const float* b2 = (const float*)d_in[5];
    const float* W3 = (const float*)d_in[6];
    const float* b3 = (const float*)d_in[7];
    float* out = (float*)d_out;

    const int TB = 256;
    // dtype probe + CSR build (edge_index is a fresh input every call)
    k_detect<<<1, 1>>>((const int*)ei);
    k_zero_cnt<<<(NN + TB - 1) / TB, TB>>>();
    k_count<<<(NE + TB - 1) / TB, TB>>>(ei);
    k_scan<<<1, 1024>>>();
    k_fill<<<(NE + TB - 1) / TB, TB>>>(ei);

    int agg_blocks = (NN * 32 + TB - 1) / TB;   // one warp per node
    dim3 mlp_grid(296, 2);

    // layer 1
    k_agg<<<agg_blocks, TB>>>((const float4*)x, 0);
    k_mlp<<<mlp_grid, 128>>>(W1, b1);
    // layer 2
    k_agg<<<agg_blocks, TB>>>(nullptr, 1);
    k_mlp<<<mlp_grid, 128>>>(W2, b2);
    // output projection
    k_final<<<agg_blocks, TB>>>(W3, b3, out);
}